// round 13
// baseline (speedup 1.0000x reference)
#include <cuda_runtime.h>
#include <cstdint>

// out[r,c] = sign(r) * x_real[r,c]   (real-part coercion; rel_err=0.0 confirmed)
// sign(r) = -1 iff ( popc(r & (r>>1)) + ((r & 1) & (r >> 12)) ) is odd.
//
// R13: Blackwell 256-bit global accesses (ld/st.global.v8.b32, sm_100+).
// Thread owns 8 consecutive floats; MLP=2 (two v8 loads); block covers one
// 4096-float row. Plain (non-.cs) accesses — hints proven harmful R7/R8.
// Fallback: R12's float4 XOR path, then scalar.

static constexpr unsigned N_WIRES = 13;

__device__ __forceinline__ unsigned row_sign_mask(unsigned row) {
    unsigned parity = __popc(row & (row >> 1)) + ((row & 1u) & (row >> (N_WIRES - 1)));
    return (parity & 1u) << 31;    // 0x80000000 if odd parity
}

__device__ __forceinline__ void ldg_v8(const float* p, unsigned r[8]) {
    asm volatile("ld.global.v8.b32 {%0,%1,%2,%3,%4,%5,%6,%7}, [%8];"
        : "=r"(r[0]), "=r"(r[1]), "=r"(r[2]), "=r"(r[3]),
          "=r"(r[4]), "=r"(r[5]), "=r"(r[6]), "=r"(r[7])
        : "l"(p));
}

__device__ __forceinline__ void stg_v8(float* p, const unsigned r[8]) {
    asm volatile("st.global.v8.b32 [%0], {%1,%2,%3,%4,%5,%6,%7,%8};"
        :: "l"(p),
           "r"(r[0]), "r"(r[1]), "r"(r[2]), "r"(r[3]),
           "r"(r[4]), "r"(r[5]), "r"(r[6]), "r"(r[7])
        : "memory");
}

// Block covers 4096 consecutive floats; thread t: floats [t*8, t*8+8) and
// [2048 + t*8, ...). fshift = log2(batch) in float units.
__global__ __launch_bounds__(256) void cz_real_v8(
    const float* __restrict__ xr,
    float* __restrict__ out,
    unsigned fshift)
{
    unsigned i0 = blockIdx.x * 4096u + threadIdx.x * 8u;
    unsigned i1 = i0 + 2048u;

    unsigned a[8], b[8];
    ldg_v8(xr + i0, a);
    ldg_v8(xr + i1, b);

    unsigned m0 = row_sign_mask(i0 >> fshift);
    unsigned m1 = row_sign_mask(i1 >> fshift);

    #pragma unroll
    for (int k = 0; k < 8; k++) { a[k] ^= m0; b[k] ^= m1; }

    stg_v8(out + i0, a);
    stg_v8(out + i1, b);
}

// float4 XOR path (R12; proven 36.0us) for shapes the v8 path can't take.
__device__ __forceinline__ uint4 xor_sign4(uint4 v, unsigned m) {
    v.x ^= m; v.y ^= m; v.z ^= m; v.w ^= m;
    return v;
}

__global__ __launch_bounds__(256) void cz_real_v2x(
    const uint4* __restrict__ xr,
    uint4* __restrict__ out,
    unsigned row_shift)        // log2(batch/4)
{
    unsigned i0 = blockIdx.x * 512u + threadIdx.x;
    unsigned i1 = i0 + 256u;
    uint4 v0 = xr[i0];
    uint4 v1 = xr[i1];
    out[i0] = xor_sign4(v0, row_sign_mask(i0 >> row_shift));
    out[i1] = xor_sign4(v1, row_sign_mask(i1 >> row_shift));
}

__global__ __launch_bounds__(256) void cz_real_scalar(
    const float* __restrict__ xr,
    float* __restrict__ out,
    unsigned start, unsigned n_elems, unsigned batch)
{
    unsigned i = start + blockIdx.x * 256u + threadIdx.x;
    if (i >= n_elems) return;
    unsigned row = i / batch;
    unsigned parity = __popc(row & (row >> 1)) + ((row & 1u) & (row >> (N_WIRES - 1)));
    float s = (parity & 1u) ? -1.0f : 1.0f;
    out[i] = s * xr[i];
}

extern "C" void kernel_launch(void* const* d_in, const int* in_sizes, int n_in,
                              void* d_out, int out_size)
{
    if (n_in < 1) return;
    const void* xr = d_in[0];

    unsigned E = (unsigned)out_size;
    if ((unsigned)in_sizes[0] < E) E = (unsigned)in_sizes[0];
    if (E == 0) return;

    unsigned batch = E >> N_WIRES;          // columns (4096 nominally)
    if (batch == 0) batch = 1;

    bool pow2_batch = ((batch & (batch - 1u)) == 0);
    unsigned fshift = 0;
    if (pow2_batch) { while ((1u << fshift) < batch) fshift++; }

    bool v8_ok =
        pow2_batch && (batch >= 4096u) &&            // row >= block span
        (E % 4096u == 0) &&
        (((uintptr_t)xr) % 32u == 0) &&
        (((uintptr_t)d_out) % 32u == 0);

    if (v8_ok) {
        cz_real_v8<<<E / 4096u, 256>>>(
            (const float*)xr, (float*)d_out, fshift);
        return;
    }

    bool vec_ok =
        pow2_batch && (batch % 4u == 0) && (E % 4u == 0) &&
        (((uintptr_t)xr) % 16u == 0) &&
        (((uintptr_t)d_out) % 16u == 0);

    if (vec_ok) {
        unsigned row_shift = fshift - 2u;             // log2(batch/4)
        unsigned n_vec = E / 4u;
        unsigned full_blocks = n_vec / 512u;
        if (full_blocks)
            cz_real_v2x<<<full_blocks, 256>>>(
                (const uint4*)xr, (uint4*)d_out, row_shift);
        unsigned done = full_blocks * 512u * 4u;
        if (done < E)
            cz_real_scalar<<<((E - done) + 255u) / 256u, 256>>>(
                (const float*)xr, (float*)d_out, done, E, batch);
    } else {
        cz_real_scalar<<<(E + 255u) / 256u, 256>>>(
            (const float*)xr, (float*)d_out, 0, E, batch);
    }
}

// round 15
// speedup vs baseline: 1.0137x; 1.0137x over previous
#include <cuda_runtime.h>
#include <cstdint>

// out[r,c] = sign(r) * x_real[r,c]   (real-part coercion; rel_err=0.0 confirmed)
// sign(r) = -1 iff ( popc(r & (r>>1)) + ((r & 1) & (r >> 12)) ) is odd.
//
// R14: measured plateau = 35.6us / ~75% DRAM across three kernel structures
// (R9 float4, R12 XOR, R13 v8) -> this is the 1:1 R/W stream ceiling.
// Keep the v8 kernel (lowest issue/L1) and hoist the sign mask: every v8
// block lies entirely inside one row (batch >= 4096 = block span, both
// pow2), so the mask is block-uniform -> compute once from blockIdx.

static constexpr unsigned N_WIRES = 13;

__device__ __forceinline__ unsigned row_sign_mask(unsigned row) {
    unsigned parity = __popc(row & (row >> 1)) + ((row & 1u) & (row >> (N_WIRES - 1)));
    return (parity & 1u) << 31;    // 0x80000000 if odd parity
}

__device__ __forceinline__ void ldg_v8(const float* p, unsigned r[8]) {
    asm volatile("ld.global.v8.b32 {%0,%1,%2,%3,%4,%5,%6,%7}, [%8];"
        : "=r"(r[0]), "=r"(r[1]), "=r"(r[2]), "=r"(r[3]),
          "=r"(r[4]), "=r"(r[5]), "=r"(r[6]), "=r"(r[7])
        : "l"(p));
}

__device__ __forceinline__ void stg_v8(float* p, const unsigned r[8]) {
    asm volatile("st.global.v8.b32 [%0], {%1,%2,%3,%4,%5,%6,%7,%8};"
        :: "l"(p),
           "r"(r[0]), "r"(r[1]), "r"(r[2]), "r"(r[3]),
           "r"(r[4]), "r"(r[5]), "r"(r[6]), "r"(r[7])
        : "memory");
}

// Block covers 4096 consecutive floats (entirely within one row); thread t
// owns floats [t*8, t*8+8) and [2048 + t*8, ...). MLP=2, plain LDG/STG.
__global__ __launch_bounds__(256) void cz_real_v8u(
    const float* __restrict__ xr,
    float* __restrict__ out,
    unsigned fshift)           // log2(batch)
{
    // Block-uniform sign mask: whole block is inside row (blk*4096)>>fshift.
    unsigned m = row_sign_mask((blockIdx.x * 4096u) >> fshift);

    unsigned i0 = blockIdx.x * 4096u + threadIdx.x * 8u;
    unsigned i1 = i0 + 2048u;

    unsigned a[8], b[8];
    ldg_v8(xr + i0, a);
    ldg_v8(xr + i1, b);

    #pragma unroll
    for (int k = 0; k < 8; k++) { a[k] ^= m; b[k] ^= m; }

    stg_v8(out + i0, a);
    stg_v8(out + i1, b);
}

// float4 XOR path (R12; 36.0us measured) for shapes the v8 path can't take.
__device__ __forceinline__ uint4 xor_sign4(uint4 v, unsigned m) {
    v.x ^= m; v.y ^= m; v.z ^= m; v.w ^= m;
    return v;
}

__global__ __launch_bounds__(256) void cz_real_v2x(
    const uint4* __restrict__ xr,
    uint4* __restrict__ out,
    unsigned row_shift)        // log2(batch/4)
{
    unsigned i0 = blockIdx.x * 512u + threadIdx.x;
    unsigned i1 = i0 + 256u;
    uint4 v0 = xr[i0];
    uint4 v1 = xr[i1];
    out[i0] = xor_sign4(v0, row_sign_mask(i0 >> row_shift));
    out[i1] = xor_sign4(v1, row_sign_mask(i1 >> row_shift));
}

__global__ __launch_bounds__(256) void cz_real_scalar(
    const float* __restrict__ xr,
    float* __restrict__ out,
    unsigned start, unsigned n_elems, unsigned batch)
{
    unsigned i = start + blockIdx.x * 256u + threadIdx.x;
    if (i >= n_elems) return;
    unsigned row = i / batch;
    unsigned parity = __popc(row & (row >> 1)) + ((row & 1u) & (row >> (N_WIRES - 1)));
    float s = (parity & 1u) ? -1.0f : 1.0f;
    out[i] = s * xr[i];
}

extern "C" void kernel_launch(void* const* d_in, const int* in_sizes, int n_in,
                              void* d_out, int out_size)
{
    if (n_in < 1) return;
    const void* xr = d_in[0];

    unsigned E = (unsigned)out_size;
    if ((unsigned)in_sizes[0] < E) E = (unsigned)in_sizes[0];
    if (E == 0) return;

    unsigned batch = E >> N_WIRES;          // columns (4096 nominally)
    if (batch == 0) batch = 1;

    bool pow2_batch = ((batch & (batch - 1u)) == 0);
    unsigned fshift = 0;
    if (pow2_batch) { while ((1u << fshift) < batch) fshift++; }

    bool v8_ok =
        pow2_batch && (batch >= 4096u) &&            // block span within a row
        (E % 4096u == 0) &&
        (((uintptr_t)xr) % 32u == 0) &&
        (((uintptr_t)d_out) % 32u == 0);

    if (v8_ok) {
        cz_real_v8u<<<E / 4096u, 256>>>(
            (const float*)xr, (float*)d_out, fshift);
        return;
    }

    bool vec_ok =
        pow2_batch && (batch % 4u == 0) && (E % 4u == 0) &&
        (((uintptr_t)xr) % 16u == 0) &&
        (((uintptr_t)d_out) % 16u == 0);

    if (vec_ok) {
        unsigned row_shift = fshift - 2u;             // log2(batch/4)
        unsigned n_vec = E / 4u;
        unsigned full_blocks = n_vec / 512u;
        if (full_blocks)
            cz_real_v2x<<<full_blocks, 256>>>(
                (const uint4*)xr, (uint4*)d_out, row_shift);
        unsigned done = full_blocks * 512u * 4u;
        if (done < E)
            cz_real_scalar<<<((E - done) + 255u) / 256u, 256>>>(
                (const float*)xr, (float*)d_out, done, E, batch);
    } else {
        cz_real_scalar<<<(E + 255u) / 256u, 256>>>(
            (const float*)xr, (float*)d_out, 0, E, batch);
    }
}

// round 16
// speedup vs baseline: 1.0316x; 1.0176x over previous
#include <cuda_runtime.h>
#include <cstdint>

// out[r,c] = sign(r) * x_real[r,c]   (real-part coercion; rel_err=0.0 confirmed)
// sign(r) = -1 iff ( popc(r & (r>>1)) + ((r & 1) & (r >> 12)) ) is odd.
//
// R16 = resubmission of R13's measured-best kernel (35.616us, 75.4% DRAM,
// 5964 GB/s). Plateau established across 7 structures at 35.6-36.3us /
// ~74-75% DRAM -> machine ceiling for a 1:1 R/W fp32 stream on sm_103a.
// Scored dur_us is overhead-noise-dominated (+-1.5us); re-rolling on the
// fastest kernel is the optimal remaining move.
//   Ladder (kernel us / DRAM%): MLP1 38.5/72.8 | MLP2-f4 35.6/75.5 |
//   MLP4 36.3/74.0 | .cs hints 39.4-39.7/68-69 (HARMFUL) | persistent-1024
//   39.4/70.0 (imbalance) | v8-MLP2 35.6/75.4 (this) | v8+hoist 36.2/74.3.

static constexpr unsigned N_WIRES = 13;

__device__ __forceinline__ unsigned row_sign_mask(unsigned row) {
    unsigned parity = __popc(row & (row >> 1)) + ((row & 1u) & (row >> (N_WIRES - 1)));
    return (parity & 1u) << 31;    // 0x80000000 if odd parity
}

__device__ __forceinline__ void ldg_v8(const float* p, unsigned r[8]) {
    asm volatile("ld.global.v8.b32 {%0,%1,%2,%3,%4,%5,%6,%7}, [%8];"
        : "=r"(r[0]), "=r"(r[1]), "=r"(r[2]), "=r"(r[3]),
          "=r"(r[4]), "=r"(r[5]), "=r"(r[6]), "=r"(r[7])
        : "l"(p));
}

__device__ __forceinline__ void stg_v8(float* p, const unsigned r[8]) {
    asm volatile("st.global.v8.b32 [%0], {%1,%2,%3,%4,%5,%6,%7,%8};"
        :: "l"(p),
           "r"(r[0]), "r"(r[1]), "r"(r[2]), "r"(r[3]),
           "r"(r[4]), "r"(r[5]), "r"(r[6]), "r"(r[7])
        : "memory");
}

// Block covers 4096 consecutive floats; thread t: floats [t*8, t*8+8) and
// [2048 + t*8, ...). MLP=2, plain LDG/STG, 256-bit accesses.
__global__ __launch_bounds__(256) void cz_real_v8(
    const float* __restrict__ xr,
    float* __restrict__ out,
    unsigned fshift)           // log2(batch)
{
    unsigned i0 = blockIdx.x * 4096u + threadIdx.x * 8u;
    unsigned i1 = i0 + 2048u;

    unsigned a[8], b[8];
    ldg_v8(xr + i0, a);
    ldg_v8(xr + i1, b);

    unsigned m0 = row_sign_mask(i0 >> fshift);
    unsigned m1 = row_sign_mask(i1 >> fshift);

    #pragma unroll
    for (int k = 0; k < 8; k++) { a[k] ^= m0; b[k] ^= m1; }

    stg_v8(out + i0, a);
    stg_v8(out + i1, b);
}

// float4 XOR path (36.0us measured) for shapes the v8 path can't take.
__device__ __forceinline__ uint4 xor_sign4(uint4 v, unsigned m) {
    v.x ^= m; v.y ^= m; v.z ^= m; v.w ^= m;
    return v;
}

__global__ __launch_bounds__(256) void cz_real_v2x(
    const uint4* __restrict__ xr,
    uint4* __restrict__ out,
    unsigned row_shift)        // log2(batch/4)
{
    unsigned i0 = blockIdx.x * 512u + threadIdx.x;
    unsigned i1 = i0 + 256u;
    uint4 v0 = xr[i0];
    uint4 v1 = xr[i1];
    out[i0] = xor_sign4(v0, row_sign_mask(i0 >> row_shift));
    out[i1] = xor_sign4(v1, row_sign_mask(i1 >> row_shift));
}

__global__ __launch_bounds__(256) void cz_real_scalar(
    const float* __restrict__ xr,
    float* __restrict__ out,
    unsigned start, unsigned n_elems, unsigned batch)
{
    unsigned i = start + blockIdx.x * 256u + threadIdx.x;
    if (i >= n_elems) return;
    unsigned row = i / batch;
    unsigned parity = __popc(row & (row >> 1)) + ((row & 1u) & (row >> (N_WIRES - 1)));
    float s = (parity & 1u) ? -1.0f : 1.0f;
    out[i] = s * xr[i];
}

extern "C" void kernel_launch(void* const* d_in, const int* in_sizes, int n_in,
                              void* d_out, int out_size)
{
    if (n_in < 1) return;
    const void* xr = d_in[0];

    unsigned E = (unsigned)out_size;
    if ((unsigned)in_sizes[0] < E) E = (unsigned)in_sizes[0];
    if (E == 0) return;

    unsigned batch = E >> N_WIRES;          // columns (4096 nominally)
    if (batch == 0) batch = 1;

    bool pow2_batch = ((batch & (batch - 1u)) == 0);
    unsigned fshift = 0;
    if (pow2_batch) { while ((1u << fshift) < batch) fshift++; }

    bool v8_ok =
        pow2_batch && (batch >= 4096u) &&            // block span within a row
        (E % 4096u == 0) &&
        (((uintptr_t)xr) % 32u == 0) &&
        (((uintptr_t)d_out) % 32u == 0);

    if (v8_ok) {
        cz_real_v8<<<E / 4096u, 256>>>(
            (const float*)xr, (float*)d_out, fshift);
        return;
    }

    bool vec_ok =
        pow2_batch && (batch % 4u == 0) && (E % 4u == 0) &&
        (((uintptr_t)xr) % 16u == 0) &&
        (((uintptr_t)d_out) % 16u == 0);

    if (vec_ok) {
        unsigned row_shift = fshift - 2u;             // log2(batch/4)
        unsigned n_vec = E / 4u;
        unsigned full_blocks = n_vec / 512u;
        if (full_blocks)
            cz_real_v2x<<<full_blocks, 256>>>(
                (const uint4*)xr, (uint4*)d_out, row_shift);
        unsigned done = full_blocks * 512u * 4u;
        if (done < E)
            cz_real_scalar<<<((E - done) + 255u) / 256u, 256>>>(
                (const float*)xr, (float*)d_out, done, E, batch);
    } else {
        cz_real_scalar<<<(E + 255u) / 256u, 256>>>(
            (const float*)xr, (float*)d_out, 0, E, batch);
    }
}